// round 5
// baseline (speedup 1.0000x reference)
#include <cuda_runtime.h>

// FixedFoveatedSensor: out[b,c,h,w] = sum_s bilinear(img, warp(pos_s)) * det_s / sum_s det_s
// img: (4,3,1024,1024) f32, t: (1,) f32, jitter: (16,256,256,2) f32, out: (4,3,256,256) f32
// One thread per sensor pixel: all 16 spp + all 12 (b,c) channels accumulated locally.
// No shuffles, no shared memory, no early returns -> zero deadlock surface.

#define SPP 16
#define SH 256
#define SW 256
#define NBC 12
#define IMG_H 1024
#define IMG_W 1024

__global__ __launch_bounds__(256)
void ffs_kernel(const float* __restrict__ img,
                const float* __restrict__ t,
                const float* __restrict__ jitter,
                float* __restrict__ out)
{
    const int pixel = blockIdx.x * blockDim.x + threadIdx.x;   // grid exactly covers 65536
    const int h = pixel >> 8;
    const int w = pixel & 255;

    const float tt    = t[0];
    const float s_inv = 1.0f / tanhf(tt);
    const float step  = 2.0f / 256.0f;
    const float base_x = -1.0f + (float)w * step;
    const float base_y = -1.0f + (float)h * step;

    float acc[NBC];
#pragma unroll
    for (int i = 0; i < NBC; i++) acc[i] = 0.0f;
    float accDet = 0.0f;

#pragma unroll 4
    for (int s = 0; s < SPP; s++) {
        const float2 jit = *(const float2*)(jitter + (((size_t)s * SH + h) * SW + w) * 2);
        const float posx = fmaf(jit.x, step, base_x);
        const float posy = fmaf(jit.y, step, base_y);

        const float thx = tanhf(tt * posx);
        const float thy = tanhf(tt * posy);
        const float wrx = thx * s_inv;
        const float wry = thy * s_inv;
        const float ddx = tt * (1.0f - thx * thx) * s_inv;
        const float ddy = tt * (1.0f - thy * thy) * s_inv;
        const float det = ddx * ddy;
        accDet += det;

        float gx = (wrx + 1.0f) * (0.5f * IMG_W) - 0.5f;
        float gy = (wry + 1.0f) * (0.5f * IMG_H) - 0.5f;
        gx = fminf(fmaxf(gx, 0.0f), (float)(IMG_W - 1));
        gy = fminf(fmaxf(gy, 0.0f), (float)(IMG_H - 1));
        const float x0f = floorf(gx);
        const float y0f = floorf(gy);
        const float fx = gx - x0f;
        const float fy = gy - y0f;
        const int x0 = (int)x0f;
        const int y0 = (int)y0f;
        const int x1 = min(x0 + 1, IMG_W - 1);
        const int y1 = min(y0 + 1, IMG_H - 1);

        // fold det into bilinear weights
        const float w11 = fx * fy * det;
        const float w01 = fx * det - w11;
        const float w10 = fy * det - w11;
        const float w00 = det - w01 - w10 - w11;

        const int i00 = y0 * IMG_W + x0;
        const int i01 = y0 * IMG_W + x1;
        const int i10 = y1 * IMG_W + x0;
        const int i11 = y1 * IMG_W + x1;

#pragma unroll
        for (int bc = 0; bc < NBC; bc++) {
            const float* p = img + (size_t)bc * (IMG_H * IMG_W);
            float v = p[i00] * w00;
            v = fmaf(p[i01], w01, v);
            v = fmaf(p[i10], w10, v);
            v = fmaf(p[i11], w11, v);
            acc[bc] += v;
        }
    }

    const float inv = 1.0f / accDet;
#pragma unroll
    for (int bc = 0; bc < NBC; bc++)
        out[(size_t)bc * (SH * SW) + pixel] = acc[bc] * inv;
}

extern "C" void kernel_launch(void* const* d_in, const int* in_sizes, int n_in,
                              void* d_out, int out_size)
{
    const float* img    = (const float*)d_in[0];
    const float* t      = (const float*)d_in[1];
    const float* jitter = (const float*)d_in[2];
    float* out          = (float*)d_out;

    ffs_kernel<<<(SH * SW) / 256, 256>>>(img, t, jitter, out);
}

// round 6
// speedup vs baseline: 1.4246x; 1.4246x over previous
#include <cuda_runtime.h>

// FixedFoveatedSensor: out[b,c,h,w] = sum_s bilinear(img, warp(pos_s)) * det_s / sum_s det_s
// img: (4,3,1024,1024) f32, t: (1,) f32, jitter: (16,256,256,2) f32, out: (4,3,256,256) f32
//
// Channel-split parallelization: 4 thread-groups per pixel, each handling 3 of the
// 12 (b,c) planes. Coordinates/det recomputed per group (fma pipe is nearly idle);
// zero cross-thread communication. 262144 threads -> ~85% occupancy vs 21% before.

#define SPP 16
#define SH 256
#define SW 256
#define NBC 12
#define CH_PER_GROUP 3
#define NGROUPS 4
#define IMG_H 1024
#define IMG_W 1024

__global__ __launch_bounds__(256)
void ffs_kernel(const float* __restrict__ img,
                const float* __restrict__ t,
                const float* __restrict__ jitter,
                float* __restrict__ out)
{
    const int tid   = blockIdx.x * blockDim.x + threadIdx.x;
    const int pixel = tid & (SH * SW - 1);      // fast dim: adjacent lanes = adjacent pixels
    const int grp   = tid >> 16;                // 0..3, which 3-channel group
    const int h = pixel >> 8;
    const int w = pixel & 255;

    const float tt    = t[0];
    const float s_inv = 1.0f / tanhf(tt);
    const float step  = 2.0f / 256.0f;
    const float base_x = -1.0f + (float)w * step;
    const float base_y = -1.0f + (float)h * step;

    const float* __restrict__ plane0 = img + (size_t)(grp * CH_PER_GROUP) * (IMG_H * IMG_W);

    float acc0 = 0.0f, acc1 = 0.0f, acc2 = 0.0f;
    float accDet = 0.0f;

#pragma unroll 4
    for (int s = 0; s < SPP; s++) {
        const float2 jit = *(const float2*)(jitter + (((size_t)s * SH + h) * SW + w) * 2);
        const float posx = fmaf(jit.x, step, base_x);
        const float posy = fmaf(jit.y, step, base_y);

        const float thx = tanhf(tt * posx);
        const float thy = tanhf(tt * posy);
        const float wrx = thx * s_inv;
        const float wry = thy * s_inv;
        const float ddx = tt * (1.0f - thx * thx) * s_inv;
        const float ddy = tt * (1.0f - thy * thy) * s_inv;
        const float det = ddx * ddy;
        accDet += det;

        float gx = (wrx + 1.0f) * (0.5f * IMG_W) - 0.5f;
        float gy = (wry + 1.0f) * (0.5f * IMG_H) - 0.5f;
        gx = fminf(fmaxf(gx, 0.0f), (float)(IMG_W - 1));
        gy = fminf(fmaxf(gy, 0.0f), (float)(IMG_H - 1));
        const float x0f = floorf(gx);
        const float y0f = floorf(gy);
        const float fx = gx - x0f;
        const float fy = gy - y0f;
        const int x0 = (int)x0f;
        const int y0 = (int)y0f;
        const int x1 = min(x0 + 1, IMG_W - 1);
        const int y1 = min(y0 + 1, IMG_H - 1);

        // fold det into bilinear weights
        const float w11 = fx * fy * det;
        const float w01 = fx * det - w11;
        const float w10 = fy * det - w11;
        const float w00 = det - w01 - w10 - w11;

        const int i00 = y0 * IMG_W + x0;
        const int i01 = y0 * IMG_W + x1;
        const int i10 = y1 * IMG_W + x0;
        const int i11 = y1 * IMG_W + x1;

#pragma unroll
        for (int c = 0; c < CH_PER_GROUP; c++) {
            const float* p = plane0 + (size_t)c * (IMG_H * IMG_W);
            float v = p[i00] * w00;
            v = fmaf(p[i01], w01, v);
            v = fmaf(p[i10], w10, v);
            v = fmaf(p[i11], w11, v);
            if (c == 0) acc0 += v;
            else if (c == 1) acc1 += v;
            else acc2 += v;
        }
    }

    const float inv = 1.0f / accDet;
    float* __restrict__ o = out + (size_t)(grp * CH_PER_GROUP) * (SH * SW) + pixel;
    o[0 * SH * SW] = acc0 * inv;
    o[1 * SH * SW] = acc1 * inv;
    o[2 * SH * SW] = acc2 * inv;
}

extern "C" void kernel_launch(void* const* d_in, const int* in_sizes, int n_in,
                              void* d_out, int out_size)
{
    const float* img    = (const float*)d_in[0];
    const float* t      = (const float*)d_in[1];
    const float* jitter = (const float*)d_in[2];
    float* out          = (float*)d_out;

    ffs_kernel<<<(SH * SW * NGROUPS) / 256, 256>>>(img, t, jitter, out);
}